// round 2
// baseline (speedup 1.0000x reference)
#include <cuda_runtime.h>
#include <math.h>

// ---------------- problem constants ----------------
#define NROWS 50000
#define NFEAT 300
#define LWORDS 16
#define EDGES 800000
#define HID 64
#define JOINT 128
#define BATCH 4096
#define ALPHA 0.2f
#define EPSV 1e-16f

// ---------------- scratch ----------------
__device__ float g_Pw[(size_t)NROWS * HID];          // word_emb @ tw_W1
__device__ float g_h1[2][(size_t)NROWS * HID];       // layer1 inputs h (tweet, user)
__device__ float g_out1[2][(size_t)NROWS * HID];     // layer1 outputs
__device__ float g_h2[2][(size_t)NROWS * JOINT];     // layer2 h
__device__ float g_X[2][(size_t)NROWS * JOINT];      // final view features
__device__ float g_f[2][NROWS];
__device__ float g_g[2][NROWS];
__device__ int   g_cnt[2][NROWS];
__device__ int   g_incl[2][NROWS];
__device__ int   g_rowptr[2][NROWS + 1];
__device__ int   g_tmp[2][NROWS];
__device__ int   g_cols[2][EDGES];
__device__ int   g_bsums[2][64];
__device__ int   g_bpre[2][64];
__device__ float g_att[2];

// ---------------- f32x2 helpers ----------------
__device__ __forceinline__ unsigned long long pack_dup(float a) {
    unsigned long long r;
    asm("mov.b64 %0,{%1,%1};" : "=l"(r) : "f"(a));
    return r;
}
__device__ __forceinline__ void fma_x2(unsigned long long& acc, unsigned long long a,
                                       unsigned long long b) {
    asm("fma.rn.f32x2 %0,%1,%2,%3;" : "=l"(acc) : "l"(a), "l"(b), "l"(acc));
}
__device__ __forceinline__ void unpack2(unsigned long long v, float& lo, float& hi) {
    asm("mov.b64 {%0,%1},%2;" : "=f"(lo), "=f"(hi) : "l"(v));
}

// ---------------- init ----------------
__global__ void init_k(float* att) {
    int i = blockIdx.x * blockDim.x + threadIdx.x;
    if (i < 2 * NROWS) ((int*)g_cnt)[i] = 0;
    if (i < 2) att[i] = 0.0f;
}

// ---------------- CSR build (both graphs batched) ----------------
__global__ void count_k(const int* __restrict__ r0, const int* __restrict__ r1) {
    int e = blockIdx.x * blockDim.x + threadIdx.x;
    if (e < EDGES) atomicAdd(&g_cnt[0][r0[e]], 1);
    else if (e < 2 * EDGES) atomicAdd(&g_cnt[1][r1[e - EDGES]], 1);
}

__global__ void scan_block_k() {
    __shared__ int sm[1024];
    int gidx = blockIdx.y;
    int i = blockIdx.x * 1024 + threadIdx.x;
    int v = (i < NROWS) ? g_cnt[gidx][i] : 0;
    sm[threadIdx.x] = v;
    __syncthreads();
#pragma unroll
    for (int o = 1; o < 1024; o <<= 1) {
        int t = (threadIdx.x >= o) ? sm[threadIdx.x - o] : 0;
        __syncthreads();
        sm[threadIdx.x] += t;
        __syncthreads();
    }
    if (i < NROWS) g_incl[gidx][i] = sm[threadIdx.x];
    if (threadIdx.x == 1023) g_bsums[gidx][blockIdx.x] = sm[1023];
}

__global__ void scan_sums_k(int nb) {
    int gidx = threadIdx.x;
    if (gidx < 2) {
        int run = 0;
        for (int i = 0; i < nb; i++) { g_bpre[gidx][i] = run; run += g_bsums[gidx][i]; }
    }
}

__global__ void finalize_csr_k() {
    int gidx = blockIdx.y;
    int i = blockIdx.x * blockDim.x + threadIdx.x;
    if (i < NROWS) {
        int ex = g_incl[gidx][i] - g_cnt[gidx][i] + g_bpre[gidx][i >> 10];
        g_rowptr[gidx][i] = ex;
        g_tmp[gidx][i] = ex;
    }
    if (i == 0) g_rowptr[gidx][NROWS] = EDGES;
}

__global__ void scatter_k(const int* __restrict__ e0, const int* __restrict__ e1) {
    int e = blockIdx.x * blockDim.x + threadIdx.x;
    if (e < EDGES) {
        int r = e0[e];
        int p = atomicAdd(&g_tmp[0][r], 1);
        g_cols[0][p] = e0[e + EDGES];
    } else if (e < 2 * EDGES) {
        int ee = e - EDGES;
        int r = e1[ee];
        int p = atomicAdd(&g_tmp[1][r], 1);
        g_cols[1][p] = e1[ee + EDGES];
    }
}

// ---------------- GEMM with packed f32x2, optional f/g fusion, optional tanh-reduce ----------------
// C[M,BN] = A[M,K] @ B[K,BN]; grid.y picks view (pointer pairs).
// MODE 0: store C (+ optionally f/g if av != nullptr)
// MODE 1: tanh-proj reduction into red (no C store)
template <int BM, int BN, int BK, int TM, int TN, int MODE>
__global__ void gemm_k(const float* __restrict__ A0, const float* __restrict__ A1,
                       const float* __restrict__ B0, const float* __restrict__ B1,
                       float* __restrict__ C0, float* __restrict__ C1,
                       int M, int K,
                       const float* __restrict__ av0, const float* __restrict__ av1,
                       const float* __restrict__ proj, float* __restrict__ red) {
    constexpr int TX = BN / TN;
    constexpr int TY = BM / TM;
    constexpr int NT = TX * TY;
    __shared__ __align__(16) float As[BM][BK + 1];
    __shared__ __align__(16) float Bs[BK][BN];

    int view = blockIdx.y;
    const float* A = view ? A1 : A0;
    const float* Bm = view ? B1 : B0;
    float* C = view ? C1 : C0;
    const float* av = view ? av1 : av0;

    int tid = threadIdx.x;
    int tx = tid % TX;
    int ty = tid / TX;
    int m0 = blockIdx.x * BM;

    unsigned long long acc2[TM][TN / 2];
#pragma unroll
    for (int i = 0; i < TM; i++)
#pragma unroll
        for (int j = 0; j < TN / 2; j++) acc2[i][j] = 0ULL;

    int nk = (K + BK - 1) / BK;
    for (int kb = 0; kb < nk; kb++) {
        int k0 = kb * BK;
#pragma unroll
        for (int t = tid; t < BM * BK; t += NT) {
            int m = t / BK, k = t % BK;
            float v = 0.0f;
            if (m0 + m < M && k0 + k < K) v = A[(size_t)(m0 + m) * K + (k0 + k)];
            As[m][k] = v;
        }
#pragma unroll
        for (int t = tid; t < BK * BN; t += NT) {
            int k = t / BN, n = t % BN;
            float v = 0.0f;
            if (k0 + k < K) v = Bm[(size_t)(k0 + k) * BN + n];
            Bs[k][n] = v;
        }
        __syncthreads();
#pragma unroll
        for (int k = 0; k < BK; k++) {
            unsigned long long apk[TM];
#pragma unroll
            for (int i = 0; i < TM; i++) apk[i] = pack_dup(As[ty * TM + i][k]);
            unsigned long long bpk[TN / 2];
#pragma unroll
            for (int j = 0; j < TN; j += 4) {
                ulonglong2 u = *reinterpret_cast<const ulonglong2*>(&Bs[k][tx * TN + j]);
                bpk[j / 2] = u.x;
                bpk[j / 2 + 1] = u.y;
            }
#pragma unroll
            for (int i = 0; i < TM; i++)
#pragma unroll
                for (int j = 0; j < TN / 2; j++) fma_x2(acc2[i][j], apk[i], bpk[j]);
        }
        __syncthreads();
    }

    // unpack accumulators
    float val[TM][TN];
#pragma unroll
    for (int i = 0; i < TM; i++)
#pragma unroll
        for (int j = 0; j < TN / 2; j++) unpack2(acc2[i][j], val[i][2 * j], val[i][2 * j + 1]);

    if (MODE == 0) {
#pragma unroll
        for (int i = 0; i < TM; i++) {
            int m = m0 + ty * TM + i;
            if (m < M) {
#pragma unroll
                for (int j = 0; j < TN; j += 4) {
                    float4 v4 = make_float4(val[i][j], val[i][j + 1], val[i][j + 2], val[i][j + 3]);
                    *reinterpret_cast<float4*>(&C[(size_t)m * BN + tx * TN + j]) = v4;
                }
            }
        }
        if (av != nullptr) {
            // fused f/g: each row lives in TX=16 consecutive lanes
            float* fo = g_f[view];
            float* go = g_g[view];
#pragma unroll
            for (int i = 0; i < TM; i++) {
                float sf = 0.0f, sg = 0.0f;
#pragma unroll
                for (int j = 0; j < TN; j++) {
                    int c = tx * TN + j;
                    sf = fmaf(val[i][j], av[c], sf);
                    sg = fmaf(val[i][j], av[BN + c], sg);
                }
#pragma unroll
                for (int o = TX / 2; o; o >>= 1) {
                    sf += __shfl_xor_sync(0xffffffffu, sf, o);
                    sg += __shfl_xor_sync(0xffffffffu, sg, o);
                }
                int m = m0 + ty * TM + i;
                if (tx == 0 && m < M) { fo[m] = sf; go[m] = sg; }
            }
        }
    } else {
        // tanh(val) dotted with proj, summed over tile; OOB rows give tanh(0)=0
        float s = 0.0f;
#pragma unroll
        for (int j = 0; j < TN; j++) {
            float pj = proj[tx * TN + j];
#pragma unroll
            for (int i = 0; i < TM; i++) s = fmaf(tanhf(val[i][j]), pj, s);
        }
#pragma unroll
        for (int o = 16; o; o >>= 1) s += __shfl_xor_sync(0xffffffffu, s, o);
        __shared__ float wred[NT / 32];
        if ((tid & 31) == 0) wred[tid >> 5] = s;
        __syncthreads();
        if (tid == 0) {
            float tot = 0.0f;
            for (int w = 0; w < NT / 32; w++) tot += wred[w];
            atomicAdd(red + view, tot);
        }
    }
}

// ---------------- gather-mean + fused f/g (tweet view) ----------------
// warp per row; lane covers cols {lane, lane+32} of HID=64.
__global__ void gather_mean_fg_k(const int* __restrict__ idx, const float* __restrict__ P,
                                 float* __restrict__ out, const float* __restrict__ a) {
    int row = (blockIdx.x * blockDim.x + threadIdx.x) >> 5;
    int lane = threadIdx.x & 31;
    if (row >= NROWS) return;
    int w = idx[row * LWORDS + (lane & 15)];
    float acc0 = 0.0f, acc1 = 0.0f;
#pragma unroll
    for (int l = 0; l < LWORDS; l++) {
        int wl = __shfl_sync(0xffffffffu, w, l);
        acc0 += P[(size_t)wl * HID + lane];
        acc1 += P[(size_t)wl * HID + 32 + lane];
    }
    float h0 = acc0 * (1.0f / LWORDS);
    float h1 = acc1 * (1.0f / LWORDS);
    out[(size_t)row * HID + lane] = h0;
    out[(size_t)row * HID + 32 + lane] = h1;
    float sf = h0 * a[lane] + h1 * a[32 + lane];
    float sg = h0 * a[64 + lane] + h1 * a[96 + lane];
#pragma unroll
    for (int o = 16; o; o >>= 1) {
        sf += __shfl_xor_sync(0xffffffffu, sf, o);
        sg += __shfl_xor_sync(0xffffffffu, sg, o);
    }
    if (lane == 0) { g_f[0][row] = sf; g_g[0][row] = sg; }
}

// ---------------- SpGAT aggregation (both views batched via grid.y) ----------------
template <int D>
__global__ void agg_k(const float* __restrict__ h0, const float* __restrict__ h1,
                      float* __restrict__ o0, float* __restrict__ o1) {
    int view = blockIdx.y;
    int row = (blockIdx.x * blockDim.x + threadIdx.x) >> 5;
    int lane = threadIdx.x & 31;
    if (row >= NROWS) return;
    const int* rowptr = g_rowptr[view];
    const int* cols = g_cols[view];
    const float* f = g_f[view];
    const float* gg = g_g[view];
    const float* h = view ? h1 : h0;
    float* out = view ? o1 : o0;

    int s = rowptr[row];
    int e = rowptr[row + 1];
    float fr = f[row];
    constexpr int V = D / 32;
    float acc[V];
#pragma unroll
    for (int j = 0; j < V; j++) acc[j] = 0.0f;
    float den = 0.0f;
    for (int p = s; p < e; p++) {
        int c = cols[p];
        float x = fr + gg[c];
        float lr = x > 0.0f ? x : ALPHA * x;
        float w = expf(-lr);
        den += w;
        const float* hc = h + (size_t)c * D;
#pragma unroll
        for (int j = 0; j < V; j++) acc[j] = fmaf(w, hc[lane + j * 32], acc[j]);
    }
    float inv = 1.0f / (den + EPSV);
#pragma unroll
    for (int j = 0; j < V; j++) {
        float v = acc[j] * inv;
        v = v > 0.0f ? v : expm1f(v);  // ELU
        out[(size_t)row * D + lane + j * 32] = v;
    }
}

// ---------------- final fusion + classifier + log_softmax ----------------
__global__ void final_k(const float* __restrict__ twX, const float* __restrict__ tuX,
                        const int* __restrict__ g0, const int* __restrict__ g1,
                        const float* __restrict__ outW, const float* __restrict__ outB,
                        const float* __restrict__ att, float* __restrict__ out) {
    int b = (blockIdx.x * blockDim.x + threadIdx.x) >> 5;
    int lane = threadIdx.x & 31;
    if (b >= BATCH) return;
    float a0 = att[0] * (1.0f / NROWS);
    float a1 = att[1] * (1.0f / NROWS);
    float mx = fmaxf(a0, a1);
    float e0 = expf(a0 - mx), e1 = expf(a1 - mx);
    float inv = 1.0f / (e0 + e1);
    float w0 = e0 * inv, w1 = e1 * inv;
    int i0 = g0[b], i1 = g1[b];
    float l0 = 0.0f, l1 = 0.0f;
#pragma unroll
    for (int j = 0; j < JOINT / 32; j++) {
        int c = lane + j * 32;
        float fv = w0 * twX[(size_t)i0 * JOINT + c] + w1 * tuX[(size_t)i1 * JOINT + c];
        l0 = fmaf(fv, outW[c], l0);
        l1 = fmaf(fv, outW[JOINT + c], l1);
    }
#pragma unroll
    for (int o = 16; o; o >>= 1) {
        l0 += __shfl_xor_sync(0xffffffffu, l0, o);
        l1 += __shfl_xor_sync(0xffffffffu, l1, o);
    }
    if (lane == 0) {
        l0 += outB[0];
        l1 += outB[1];
        float m = fmaxf(l0, l1);
        float lse = m + logf(expf(l0 - m) + expf(l1 - m));
        out[b * 2 + 0] = l0 - lse;
        out[b * 2 + 1] = l1 - lse;
    }
}

// ---------------- host launcher ----------------
extern "C" void kernel_launch(void* const* d_in, const int* in_sizes, int n_in,
                              void* d_out, int out_size) {
    const float *word_emb, *user_emb, *tw_W1, *tw_a1, *tw_W2, *tw_a2;
    const float *tu_W1, *tu_a1, *tu_W2, *tu_a2, *weight_W, *weight_proj, *out_W, *out_b;
    const int *feat_idx, *tw_edges, *ut_edges, *tw_gidx, *ut_gidx;

    if (in_sizes[0] == NROWS * NFEAT) {
        word_emb    = (const float*)d_in[0];
        user_emb    = (const float*)d_in[1];
        tw_W1       = (const float*)d_in[2];
        tw_a1       = (const float*)d_in[3];
        tw_W2       = (const float*)d_in[4];
        tw_a2       = (const float*)d_in[5];
        tu_W1       = (const float*)d_in[6];
        tu_a1       = (const float*)d_in[7];
        tu_W2       = (const float*)d_in[8];
        tu_a2       = (const float*)d_in[9];
        weight_W    = (const float*)d_in[10];
        weight_proj = (const float*)d_in[11];
        out_W       = (const float*)d_in[12];
        out_b       = (const float*)d_in[13];
        feat_idx    = (const int*)d_in[14];
        tw_edges    = (const int*)d_in[15];
        ut_edges    = (const int*)d_in[16];
        tw_gidx     = (const int*)d_in[17];
        ut_gidx     = (const int*)d_in[18];
    } else {
        feat_idx    = (const int*)d_in[0];
        tw_edges    = (const int*)d_in[1];
        ut_edges    = (const int*)d_in[2];
        tw_gidx     = (const int*)d_in[3];
        ut_gidx     = (const int*)d_in[4];
        word_emb    = (const float*)d_in[5];
        user_emb    = (const float*)d_in[6];
        tw_W1       = (const float*)d_in[7];
        tw_a1       = (const float*)d_in[8];
        tw_W2       = (const float*)d_in[9];
        tw_a2       = (const float*)d_in[10];
        tu_W1       = (const float*)d_in[11];
        tu_a1       = (const float*)d_in[12];
        tu_W2       = (const float*)d_in[13];
        tu_a2       = (const float*)d_in[14];
        weight_W    = (const float*)d_in[15];
        weight_proj = (const float*)d_in[16];
        out_W       = (const float*)d_in[17];
        out_b       = (const float*)d_in[18];
    }

    float *Pw, *h1, *out1, *h2, *X, *att;
    cudaGetSymbolAddress((void**)&Pw, g_Pw);
    cudaGetSymbolAddress((void**)&h1, g_h1);
    cudaGetSymbolAddress((void**)&out1, g_out1);
    cudaGetSymbolAddress((void**)&h2, g_h2);
    cudaGetSymbolAddress((void**)&X, g_X);
    cudaGetSymbolAddress((void**)&att, g_att);
    float* h1_tw = h1;
    float* h1_u  = h1 + (size_t)NROWS * HID;
    float* out1_tw = out1;
    float* out1_u  = out1 + (size_t)NROWS * HID;
    float* h2_tw = h2;
    float* h2_u  = h2 + (size_t)NROWS * JOINT;
    float* X_tw = X;
    float* X_u  = X + (size_t)NROWS * JOINT;

    const int WG = (NROWS * 32 + 255) / 256;  // 6250 (warp-per-row grids)
    const int G1 = (NROWS + 127) / 128;       // 391
    const int E2 = (2 * EDGES + 255) / 256;   // 6250
    const int NB = (NROWS + 1023) / 1024;     // 49

    init_k<<<(2 * NROWS + 255) / 256, 256>>>(att);

    // CSR for both graphs
    count_k<<<E2, 256>>>(tw_edges, ut_edges);
    scan_block_k<<<dim3(NB, 2), 1024>>>();
    scan_sums_k<<<1, 32>>>(NB);
    finalize_csr_k<<<dim3((NROWS + 255) / 256, 2), 256>>>();
    scatter_k<<<E2, 256>>>(tw_edges, ut_edges);

    // GEMM1 (both views): view0 word_emb@tw_W1 -> Pw (no fg), view1 user_emb@tu_W1 -> h1_u (+fg)
    gemm_k<128, 64, 20, 8, 4, 0><<<dim3(G1, 2), 256>>>(
        word_emb, user_emb, tw_W1, tu_W1, Pw, h1_u, NROWS, NFEAT,
        nullptr, tu_a1, nullptr, nullptr);

    // tweet h1 = mean of Pw rows over 16 words, + fused fg
    gather_mean_fg_k<<<WG, 256>>>(feat_idx, Pw, h1_tw, tw_a1);

    // layer-1 aggregation (both views)
    agg_k<HID><<<dim3(WG, 2), 256>>>(h1_tw, h1_u, out1_tw, out1_u);

    // GEMM2 (both views) + fused fg with a2
    gemm_k<128, 128, 16, 8, 8, 0><<<dim3(G1, 2), 256>>>(
        out1_tw, out1_u, tw_W2, tu_W2, h2_tw, h2_u, NROWS, HID,
        tw_a2, tu_a2, nullptr, nullptr);

    // layer-2 aggregation (both views)
    agg_k<JOINT><<<dim3(WG, 2), 256>>>(h2_tw, h2_u, X_tw, X_u);

    // fused tanh(X @ weight_W) @ proj reduction -> att[view]
    gemm_k<128, 128, 16, 8, 8, 1><<<dim3(G1, 2), 256>>>(
        X_tw, X_u, weight_W, weight_W, nullptr, nullptr, NROWS, JOINT,
        nullptr, nullptr, weight_proj, att);

    // fusion + classifier
    final_k<<<(BATCH * 32 + 255) / 256, 256>>>(X_tw, X_u, tw_gidx, ut_gidx, out_W, out_b, att,
                                               (float*)d_out);
}